// round 8
// baseline (speedup 1.0000x reference)
#include <cuda_runtime.h>
#include <cuda_bf16.h>
#include <cstdint>
#include <cstddef>

#define T_STEPS 512
#define BATCH   64
#define DIMD    512
#define DIMH    512
#define N4H     2048   // 4 gates * H, packed as j' = hid*4 + gate
#define KDIM    512
#define HB      (DIMH * BATCH)
#define MROWS   (T_STEPS * BATCH)   // 32768
#define KSPLIT  1536                // 3 * 512 (bf16x3 split segments)

// ---------------- device scratch (static) ----------------------------------------
__device__ float g_Xproj[(size_t)T_STEPS * BATCH * N4H]; // 256 MB [t*B+b][j']
__device__ float g_outT[(size_t)T_STEPS * HB];           // 64 MB [t][hid][b]
__device__ float g_cT[HB];
__device__ __nv_bfloat16 g_Ap[(size_t)MROWS * KSPLIT];   // 96 MB  A' = [hi | lo | hi]
__device__ __nv_bfloat16 g_Bp[(size_t)N4H * KSPLIT];     // 6 MB   B'[j'][k] = [hi | hi | lo]
__device__ volatile unsigned g_flag[128];                // per-CTA monotone step flags

// ---------------- f32x2 helpers ---------------------------------------------------
struct __align__(16) ULL2 { unsigned long long x, y; };

static __device__ __forceinline__ unsigned long long pack2(float v) {
    unsigned long long r;
    unsigned u = __float_as_uint(v);
    asm("mov.b64 %0, {%1, %2};" : "=l"(r) : "r"(u), "r"(u));
    return r;
}
static __device__ __forceinline__ unsigned long long fma2(unsigned long long a,
                                                          unsigned long long b,
                                                          unsigned long long c) {
    unsigned long long d;
    asm("fma.rn.f32x2 %0, %1, %2, %3;" : "=l"(d) : "l"(a), "l"(b), "l"(c));
    return d;
}
static __device__ __forceinline__ unsigned long long add2(unsigned long long a,
                                                          unsigned long long b) {
    unsigned long long d;
    asm("add.rn.f32x2 %0, %1, %2;" : "=l"(d) : "l"(a), "l"(b));
    return d;
}
static __device__ __forceinline__ float lo32(unsigned long long v) {
    return __uint_as_float((unsigned)(v & 0xffffffffull));
}
static __device__ __forceinline__ float hi32(unsigned long long v) {
    return __uint_as_float((unsigned)(v >> 32));
}
static __device__ __forceinline__ float sigf(float x) {
    return __fdividef(1.0f, 1.0f + __expf(-x));
}
static __device__ __forceinline__ float tanh_(float x) {
    return 2.0f * sigf(2.0f * x) - 1.0f;
}

// ---------------- pack kernels (bf16 hi/lo split) ---------------------------------
__global__ void pack_a(const float* __restrict__ X) {
    size_t idx = (size_t)blockIdx.x * blockDim.x + threadIdx.x;
    size_t stride = (size_t)gridDim.x * blockDim.x;
    for (size_t i = idx; i < (size_t)MROWS * KDIM; i += stride) {
        size_t m = i / KDIM, k = i % KDIM;
        float x = X[i];
        __nv_bfloat16 hi = __float2bfloat16(x);
        __nv_bfloat16 lo = __float2bfloat16(x - __bfloat162float(hi));
        __nv_bfloat16* row = g_Ap + m * KSPLIT;
        row[k] = hi; row[512 + k] = lo; row[1024 + k] = hi;
    }
}
__global__ void pack_b(const float* __restrict__ Wf, const float* __restrict__ Wi,
                       const float* __restrict__ Wg, const float* __restrict__ Wo) {
    size_t idx = (size_t)blockIdx.x * blockDim.x + threadIdx.x;
    size_t stride = (size_t)gridDim.x * blockDim.x;
    for (size_t i = idx; i < (size_t)N4H * KDIM; i += stride) {
        size_t j = i / KDIM, k = i % KDIM;
        int g = (int)(j & 3), c = (int)(j >> 2);
        const float* W = (g == 0) ? Wf : (g == 1) ? Wi : (g == 2) ? Wg : Wo;
        float w = W[k * DIMH + c];
        __nv_bfloat16 hi = __float2bfloat16(w);
        __nv_bfloat16 lo = __float2bfloat16(w - __bfloat162float(hi));
        __nv_bfloat16* row = g_Bp + j * KSPLIT;
        row[k] = hi; row[512 + k] = hi; row[1024 + k] = lo;
    }
}

// ---------------- kernel: xproj GEMM via mma.sync (bf16x3, fp32 accum) ------------
#define XBM 128
#define XBN 128
#define XBK 32
#define XROWS 40

static __device__ __forceinline__ uint32_t smem_u32(const void* p) {
    uint32_t a;
    asm("{ .reg .u64 t; cvta.to.shared.u64 t, %1; cvt.u32.u64 %0, t; }" : "=r"(a) : "l"(p));
    return a;
}
static __device__ __forceinline__ void ldsm_x4(uint32_t* r, uint32_t addr) {
    asm volatile("ldmatrix.sync.aligned.m8n8.x4.shared.b16 {%0,%1,%2,%3}, [%4];"
                 : "=r"(r[0]), "=r"(r[1]), "=r"(r[2]), "=r"(r[3]) : "r"(addr));
}
static __device__ __forceinline__ void hmma16816(float* c, const uint32_t* a,
                                                 uint32_t b0, uint32_t b1) {
    asm volatile("mma.sync.aligned.m16n8k16.row.col.f32.bf16.bf16.f32 "
                 "{%0,%1,%2,%3}, {%4,%5,%6,%7}, {%8,%9}, {%0,%1,%2,%3};"
                 : "+f"(c[0]), "+f"(c[1]), "+f"(c[2]), "+f"(c[3])
                 : "r"(a[0]), "r"(a[1]), "r"(a[2]), "r"(a[3]), "r"(b0), "r"(b1));
}

__global__ __launch_bounds__(256) void xproj_mma(
        const float* __restrict__ bf, const float* __restrict__ bi,
        const float* __restrict__ bg, const float* __restrict__ bo) {
    __shared__ __nv_bfloat16 As[2][XBM * XROWS];
    __shared__ __nv_bfloat16 Bs[2][XBN * XROWS];
    __shared__ float bsm[XBN];

    const int tid  = threadIdx.x;
    const int wid  = tid >> 5;
    const int lane = tid & 31;
    const int wm   = wid & 1;
    const int wn   = wid >> 1;
    const int m0   = blockIdx.y * XBM;
    const int n0   = blockIdx.x * XBN;

    if (tid < XBN) {
        int j = n0 + tid, g = j & 3, c = j >> 2;
        bsm[tid] = (g == 0 ? bf : g == 1 ? bi : g == 2 ? bg : bo)[c];
    }

    float acc[4][4][4];
#pragma unroll
    for (int a = 0; a < 4; ++a)
#pragma unroll
        for (int b = 0; b < 4; ++b)
#pragma unroll
            for (int q = 0; q < 4; ++q) acc[a][b][q] = 0.0f;

    const int lrow = tid >> 1;
    const int lofs = (tid & 1) * 16;
    const __nv_bfloat16* asrc = g_Ap + (size_t)(m0 + lrow) * KSPLIT + lofs;
    const __nv_bfloat16* bsrc = g_Bp + (size_t)(n0 + lrow) * KSPLIT + lofs;
    const int sidx = lrow * XROWS + lofs;

    const int a_row = wm * 64 + (lane & 7) + ((lane >> 3) & 1) * 8;
    const int a_col = ((lane >> 4) & 1) * 8;
    const int b_row = wn * 32 + (lane & 7) + ((lane >> 4) & 1) * 8;
    const int b_col = ((lane >> 3) & 1) * 8;
    const uint32_t As0 = smem_u32(&As[0][0]);
    const uint32_t Bs0 = smem_u32(&Bs[0][0]);
    const uint32_t BUFA = XBM * XROWS * 2;
    const uint32_t BUFB = XBN * XROWS * 2;

    uint4 a0v = *(const uint4*)(asrc);
    uint4 a1v = *(const uint4*)(asrc + 8);
    uint4 b0v = *(const uint4*)(bsrc);
    uint4 b1v = *(const uint4*)(bsrc + 8);
    *(uint4*)&As[0][sidx]     = a0v;
    *(uint4*)&As[0][sidx + 8] = a1v;
    *(uint4*)&Bs[0][sidx]     = b0v;
    *(uint4*)&Bs[0][sidx + 8] = b1v;
    __syncthreads();

    int p = 0;
    const int NIT = KSPLIT / XBK;   // 48
    for (int it = 0; it < NIT; ++it) {
        const bool more = (it + 1) < NIT;
        if (more) {
            a0v = *(const uint4*)(asrc + (it + 1) * XBK);
            a1v = *(const uint4*)(asrc + (it + 1) * XBK + 8);
            b0v = *(const uint4*)(bsrc + (it + 1) * XBK);
            b1v = *(const uint4*)(bsrc + (it + 1) * XBK + 8);
        }

#pragma unroll
        for (int k16 = 0; k16 < 2; ++k16) {
            uint32_t af[4][4];
#pragma unroll
            for (int mt = 0; mt < 4; ++mt) {
                uint32_t addr = As0 + p * BUFA
                              + (uint32_t)(((a_row + mt * 16) * XROWS + k16 * 16 + a_col) * 2);
                ldsm_x4(af[mt], addr);
            }
            uint32_t bg2[2][4];
#pragma unroll
            for (int hf = 0; hf < 2; ++hf) {
                uint32_t addr = Bs0 + p * BUFB
                              + (uint32_t)(((b_row + hf * 16) * XROWS + k16 * 16 + b_col) * 2);
                ldsm_x4(bg2[hf], addr);
            }
#pragma unroll
            for (int mt = 0; mt < 4; ++mt)
#pragma unroll
                for (int nt = 0; nt < 4; ++nt)
                    hmma16816(acc[mt][nt], af[mt],
                              bg2[nt >> 1][(nt & 1) * 2], bg2[nt >> 1][(nt & 1) * 2 + 1]);
        }

        if (more) {
            *(uint4*)&As[p ^ 1][sidx]     = a0v;
            *(uint4*)&As[p ^ 1][sidx + 8] = a1v;
            *(uint4*)&Bs[p ^ 1][sidx]     = b0v;
            *(uint4*)&Bs[p ^ 1][sidx + 8] = b1v;
            __syncthreads();
        }
        p ^= 1;
    }

#pragma unroll
    for (int mt = 0; mt < 4; ++mt) {
#pragma unroll
        for (int nt = 0; nt < 4; ++nt) {
            int row = m0 + wm * 64 + mt * 16 + (lane >> 2);
            int cl  = wn * 32 + nt * 8 + (lane & 3) * 2;
            float2 v0 = { acc[mt][nt][0] + bsm[cl], acc[mt][nt][1] + bsm[cl + 1] };
            float2 v1 = { acc[mt][nt][2] + bsm[cl], acc[mt][nt][3] + bsm[cl + 1] };
            *(float2*)&g_Xproj[(size_t)row * N4H + n0 + cl]       = v0;
            *(float2*)&g_Xproj[(size_t)(row + 8) * N4H + n0 + cl] = v1;
        }
    }
}

// ---------------- kernel: persistent recurrence (v7, dataflow flags) ---------------
// 128 CTAs x 512 threads. CTA r: hidden units [r*4,+4). Warp w: k-slice [w*32,+32),
// batches 2*lane, 2*lane+1. NO global barrier: per-CTA monotone flag; consumer warp
// w waits only on its 8 producer CTAs (w*8..w*8+7). comb double-buffered -> one
// __syncthreads per step. Tail: 256 threads, one (u,b) output each.
#define COMB_STRIDE (16 * 32 * 17)
#define REC_SMEM_BYTES (DIMH * 16 * 4 + 2 * COMB_STRIDE * 8)   // 32768 + 139264 = 172032

__global__ __launch_bounds__(512, 1) void lstm_kernel(
        const float* __restrict__ Wf, const float* __restrict__ Wi,
        const float* __restrict__ Wg, const float* __restrict__ Wo) {
    extern __shared__ float smem[];
    float* Whs = smem;                                                   // [512][16]
    unsigned long long* comb = (unsigned long long*)(smem + DIMH * 16);  // [2][16*32][17]

    const int r    = blockIdx.x;
    const int t    = threadIdx.x;
    const int w    = t >> 5;
    const int lane = t & 31;
    const int u    = t >> 6;       // tail: unit (t<256)
    const int b    = t & 63;       // tail: batch

    __shared__ unsigned sbase;
    if (t == 0) sbase = g_flag[r];
    for (int i = t; i < DIMH * 16; i += 512) {
        int k = i >> 4;
        int cu = (i >> 2) & 3;
        int g = i & 3;
        const float* W = (g == 0) ? Wf : (g == 1) ? Wi : (g == 2) ? Wg : Wo;
        Whs[i] = W[(size_t)(DIMD + k) * DIMH + r * 4 + cu];
    }
    __syncthreads();
    const unsigned base = sbase;

    float cst = 0.0f;

    float4 xpA;
    if (t < 256) {
        xpA = __ldg((const float4*)(g_Xproj + (size_t)b * N4H + r * 16 + u * 4));
    }

    for (int step = 0; step < T_STEPS; ++step) {
        unsigned long long* cbuf = comb + (size_t)(step & 1) * COMB_STRIDE;

        if (step > 0) {
            // ---- wait for this warp's 8 producer CTAs (h rows w*32..w*32+31) ----
            {
                const unsigned tgt = base + (unsigned)step;
                const bool mine = lane < 8;
                const int p = (w << 3) + lane;
                while (!__all_sync(0xffffffffu, !mine || g_flag[mine ? p : 0] >= tgt)) { }
                __threadfence();
            }

            const float* __restrict__ hb = g_outT + (size_t)(step - 1) * HB
                                         + (w * 32) * BATCH + lane * 2;

            unsigned long long acc[16];
#pragma unroll
            for (int i = 0; i < 16; ++i) acc[i] = 0ull;

            float2 pf[4][4];
#pragma unroll
            for (int g4 = 0; g4 < 4; ++g4)
#pragma unroll
                for (int i = 0; i < 4; ++i)
                    pf[g4][i] = __ldcg((const float2*)(hb + (g4 * 4 + i) * BATCH));

#pragma unroll
            for (int qb = 0; qb < 8; ++qb) {
                float2 cv[4];
#pragma unroll
                for (int i = 0; i < 4; ++i) cv[i] = pf[qb & 3][i];
                if (qb < 4) {
#pragma unroll
                    for (int i = 0; i < 4; ++i)
                        pf[qb & 3][i] = __ldcg((const float2*)(hb + ((qb + 4) * 4 + i) * BATCH));
                }
#pragma unroll
                for (int i = 0; i < 4; ++i) {
                    const float* wq = &Whs[(w * 32 + qb * 4 + i) * 16];
                    ULL2 wA = *(const ULL2*)(wq);
                    ULL2 wB = *(const ULL2*)(wq + 4);
                    ULL2 wC = *(const ULL2*)(wq + 8);
                    ULL2 wD = *(const ULL2*)(wq + 12);
                    unsigned long long p0 = pack2(cv[i].x);
                    unsigned long long p1 = pack2(cv[i].y);
                    acc[0]  = fma2(p0, wA.x, acc[0]);
                    acc[1]  = fma2(p0, wA.y, acc[1]);
                    acc[2]  = fma2(p0, wB.x, acc[2]);
                    acc[3]  = fma2(p0, wB.y, acc[3]);
                    acc[4]  = fma2(p0, wC.x, acc[4]);
                    acc[5]  = fma2(p0, wC.y, acc[5]);
                    acc[6]  = fma2(p0, wD.x, acc[6]);
                    acc[7]  = fma2(p0, wD.y, acc[7]);
                    acc[8]  = fma2(p1, wA.x, acc[8]);
                    acc[9]  = fma2(p1, wA.y, acc[9]);
                    acc[10] = fma2(p1, wB.x, acc[10]);
                    acc[11] = fma2(p1, wB.y, acc[11]);
                    acc[12] = fma2(p1, wC.x, acc[12]);
                    acc[13] = fma2(p1, wC.y, acc[13]);
                    acc[14] = fma2(p1, wD.x, acc[14]);
                    acc[15] = fma2(p1, wD.y, acc[15]);
                }
            }

            unsigned long long* cw = cbuf + ((size_t)w * 32 + lane) * 17;
#pragma unroll
            for (int i = 0; i < 16; ++i) cw[i] = acc[i];
        }

        __syncthreads();   // comb visible to tail; also WAR guard for buf reuse

        if (t < 256) {
            unsigned long long s0 = 0, s1 = 0;
            if (step > 0) {
#pragma unroll
                for (int kh = 0; kh < 16; ++kh) {
                    const unsigned long long* cr =
                        cbuf + ((size_t)kh * 32 + (b >> 1)) * 17 + (b & 1) * 8;
                    s0 = add2(s0, cr[u * 2]);
                    s1 = add2(s1, cr[u * 2 + 1]);
                }
            }
            float zf = lo32(s0) + xpA.x, zi = hi32(s0) + xpA.y;
            float zg = lo32(s1) + xpA.z, zo = hi32(s1) + xpA.w;

            cst = sigf(zf) * cst + sigf(zi) * tanh_(zg);
            float hv = sigf(zo) * tanh_(cst);

            const int hid = r * 4 + u;
            g_outT[(size_t)step * HB + hid * BATCH + b] = hv;
            if (step == T_STEPS - 1) g_cT[hid * BATCH + b] = cst;
            if (step + 1 < T_STEPS) {
                xpA = __ldg((const float4*)(g_Xproj
                        + ((size_t)(step + 1) * BATCH + b) * N4H + r * 16 + u * 4));
            }

            // ---- publish: h rows for this step are complete ----
            asm volatile("bar.sync 1, 256;" ::: "memory");
            if (t == 0) {
                __threadfence();
                g_flag[r] = base + (unsigned)step + 1u;
            }
        }
    }
}

// ---------------- transpose outT -> out (+ hx/cx tail) ----------------------------
__global__ __launch_bounds__(256) void transpose_out(float* __restrict__ out, int out_size) {
    __shared__ float tile[32][65];
    const int tblk = blockIdx.x;
    const int h0   = blockIdx.y * 32;
    const int tx   = threadIdx.x;
    const int ty   = threadIdx.y;
    const int tid  = ty * 64 + tx;
    const int wh   = tid & 31;
    const int wb0  = tid >> 5;

    const size_t tail = (size_t)T_STEPS * BATCH * DIMH;
    const bool write_state = (size_t)out_size >= tail + 2u * BATCH * DIMH;

    if (tblk < T_STEPS) {
        const float* src = g_outT + (size_t)tblk * HB;
#pragma unroll
        for (int i = 0; i < 8; ++i) {
            int hl = i * 4 + ty;
            tile[hl][tx] = src[(size_t)(h0 + hl) * BATCH + tx];
        }
        __syncthreads();
        float* dst = out + (size_t)tblk * BATCH * DIMH;
#pragma unroll
        for (int j = 0; j < 8; ++j) {
            int bb = wb0 + j * 8;
            dst[(size_t)bb * DIMH + h0 + wh] = tile[wh][bb];
        }
    } else if (write_state) {
        const float* src = g_outT + (size_t)(T_STEPS - 1) * HB;
#pragma unroll
        for (int i = 0; i < 8; ++i) {
            int hl = i * 4 + ty;
            tile[hl][tx] = src[(size_t)(h0 + hl) * BATCH + tx];
        }
        __syncthreads();
        float* dst = out + tail;
#pragma unroll
        for (int j = 0; j < 8; ++j) {
            int bb = wb0 + j * 8;
            dst[(size_t)bb * DIMH + h0 + wh] = tile[wh][bb];
        }
        __syncthreads();
#pragma unroll
        for (int i = 0; i < 8; ++i) {
            int hl = i * 4 + ty;
            tile[hl][tx] = g_cT[(size_t)(h0 + hl) * BATCH + tx];
        }
        __syncthreads();
        float* dst2 = out + tail + (size_t)BATCH * DIMH;
#pragma unroll
        for (int j = 0; j < 8; ++j) {
            int bb = wb0 + j * 8;
            dst2[(size_t)bb * DIMH + h0 + wh] = tile[wh][bb];
        }
    }
}

// ---------------- launch ----------------------------------------------------------
extern "C" void kernel_launch(void* const* d_in, const int* in_sizes, int n_in,
                              void* d_out, int out_size) {
    const float* inputs = (const float*)d_in[0];
    const float* Wf = (const float*)d_in[1];
    const float* bf = (const float*)d_in[2];
    const float* Wi = (const float*)d_in[3];
    const float* bi = (const float*)d_in[4];
    const float* Wg = (const float*)d_in[5];
    const float* bg = (const float*)d_in[6];
    const float* Wo = (const float*)d_in[7];
    const float* bo = (const float*)d_in[8];

    pack_a<<<1024, 256>>>(inputs);
    pack_b<<<256, 256>>>(Wf, Wi, Wg, Wo);

    dim3 gx(N4H / XBN, MROWS / XBM);   // (16, 256)
    xproj_mma<<<gx, 256>>>(bf, bi, bg, bo);

    cudaFuncSetAttribute(lstm_kernel, cudaFuncAttributeMaxDynamicSharedMemorySize, REC_SMEM_BYTES);
    lstm_kernel<<<128, 512, REC_SMEM_BYTES>>>(Wf, Wi, Wg, Wo);

    transpose_out<<<dim3(T_STEPS + 1, DIMH / 32), dim3(64, 4)>>>((float*)d_out, out_size);
}

// round 9
// speedup vs baseline: 1.9160x; 1.9160x over previous
#include <cuda_runtime.h>
#include <cuda_bf16.h>
#include <cstdint>
#include <cstddef>

#define T_STEPS 512
#define BATCH   64
#define DIMD    512
#define DIMH    512
#define N4H     2048   // 4 gates * H, packed as j' = hid*4 + gate
#define KDIM    512
#define HB      (DIMH * BATCH)
#define MROWS   (T_STEPS * BATCH)   // 32768
#define KSPLIT  1536                // 3 * 512 (bf16x3 split segments)

// ---------------- device scratch (static) ----------------------------------------
__device__ float g_Xproj[(size_t)T_STEPS * BATCH * N4H]; // 256 MB [t*B+b][j']
__device__ float g_outT[(size_t)T_STEPS * HB];           // 64 MB [t][hid][b]
__device__ float g_cT[HB];
__device__ __nv_bfloat16 g_Ap[(size_t)MROWS * KSPLIT];   // 96 MB  A' = [hi | lo | hi]
__device__ __nv_bfloat16 g_Bp[(size_t)N4H * KSPLIT];     // 6 MB   B'[j'][k] = [hi | hi | lo]
__device__ unsigned long long g_tick = 0ULL;             // monotone ticket
__device__ volatile unsigned long long g_rel = 0ULL;     // monotone release

// ---------------- f32x2 helpers ---------------------------------------------------
struct __align__(16) ULL2 { unsigned long long x, y; };

static __device__ __forceinline__ unsigned long long pack2(float v) {
    unsigned long long r;
    unsigned u = __float_as_uint(v);
    asm("mov.b64 %0, {%1, %2};" : "=l"(r) : "r"(u), "r"(u));
    return r;
}
static __device__ __forceinline__ unsigned long long fma2(unsigned long long a,
                                                          unsigned long long b,
                                                          unsigned long long c) {
    unsigned long long d;
    asm("fma.rn.f32x2 %0, %1, %2, %3;" : "=l"(d) : "l"(a), "l"(b), "l"(c));
    return d;
}
static __device__ __forceinline__ unsigned long long add2(unsigned long long a,
                                                          unsigned long long b) {
    unsigned long long d;
    asm("add.rn.f32x2 %0, %1, %2;" : "=l"(d) : "l"(a), "l"(b));
    return d;
}
static __device__ __forceinline__ float lo32(unsigned long long v) {
    return __uint_as_float((unsigned)(v & 0xffffffffull));
}
static __device__ __forceinline__ float hi32(unsigned long long v) {
    return __uint_as_float((unsigned)(v >> 32));
}
static __device__ __forceinline__ float sigf(float x) {
    return __fdividef(1.0f, 1.0f + __expf(-x));
}
static __device__ __forceinline__ float tanh_(float x) {
    return 2.0f * sigf(2.0f * x) - 1.0f;
}

// ---------------- pack kernels (bf16 hi/lo split) ---------------------------------
__global__ void pack_a(const float* __restrict__ X) {
    size_t idx = (size_t)blockIdx.x * blockDim.x + threadIdx.x;
    size_t stride = (size_t)gridDim.x * blockDim.x;
    for (size_t i = idx; i < (size_t)MROWS * KDIM; i += stride) {
        size_t m = i / KDIM, k = i % KDIM;
        float x = X[i];
        __nv_bfloat16 hi = __float2bfloat16(x);
        __nv_bfloat16 lo = __float2bfloat16(x - __bfloat162float(hi));
        __nv_bfloat16* row = g_Ap + m * KSPLIT;
        row[k] = hi; row[512 + k] = lo; row[1024 + k] = hi;
    }
}
__global__ void pack_b(const float* __restrict__ Wf, const float* __restrict__ Wi,
                       const float* __restrict__ Wg, const float* __restrict__ Wo) {
    size_t idx = (size_t)blockIdx.x * blockDim.x + threadIdx.x;
    size_t stride = (size_t)gridDim.x * blockDim.x;
    for (size_t i = idx; i < (size_t)N4H * KDIM; i += stride) {
        size_t j = i / KDIM, k = i % KDIM;
        int g = (int)(j & 3), c = (int)(j >> 2);
        const float* W = (g == 0) ? Wf : (g == 1) ? Wi : (g == 2) ? Wg : Wo;
        float w = W[k * DIMH + c];
        __nv_bfloat16 hi = __float2bfloat16(w);
        __nv_bfloat16 lo = __float2bfloat16(w - __bfloat162float(hi));
        __nv_bfloat16* row = g_Bp + j * KSPLIT;
        row[k] = hi; row[512 + k] = hi; row[1024 + k] = lo;
    }
}

// ---------------- kernel: xproj GEMM via mma.sync (bf16x3, fp32 accum) ------------
#define XBM 128
#define XBN 128
#define XBK 32
#define XROWS 40

static __device__ __forceinline__ uint32_t smem_u32(const void* p) {
    uint32_t a;
    asm("{ .reg .u64 t; cvta.to.shared.u64 t, %1; cvt.u32.u64 %0, t; }" : "=r"(a) : "l"(p));
    return a;
}
static __device__ __forceinline__ void ldsm_x4(uint32_t* r, uint32_t addr) {
    asm volatile("ldmatrix.sync.aligned.m8n8.x4.shared.b16 {%0,%1,%2,%3}, [%4];"
                 : "=r"(r[0]), "=r"(r[1]), "=r"(r[2]), "=r"(r[3]) : "r"(addr));
}
static __device__ __forceinline__ void hmma16816(float* c, const uint32_t* a,
                                                 uint32_t b0, uint32_t b1) {
    asm volatile("mma.sync.aligned.m16n8k16.row.col.f32.bf16.bf16.f32 "
                 "{%0,%1,%2,%3}, {%4,%5,%6,%7}, {%8,%9}, {%0,%1,%2,%3};"
                 : "+f"(c[0]), "+f"(c[1]), "+f"(c[2]), "+f"(c[3])
                 : "r"(a[0]), "r"(a[1]), "r"(a[2]), "r"(a[3]), "r"(b0), "r"(b1));
}

__global__ __launch_bounds__(256) void xproj_mma(
        const float* __restrict__ bf, const float* __restrict__ bi,
        const float* __restrict__ bg, const float* __restrict__ bo) {
    __shared__ __nv_bfloat16 As[2][XBM * XROWS];
    __shared__ __nv_bfloat16 Bs[2][XBN * XROWS];
    __shared__ float bsm[XBN];

    const int tid  = threadIdx.x;
    const int wid  = tid >> 5;
    const int lane = tid & 31;
    const int wm   = wid & 1;
    const int wn   = wid >> 1;
    const int m0   = blockIdx.y * XBM;
    const int n0   = blockIdx.x * XBN;

    if (tid < XBN) {
        int j = n0 + tid, g = j & 3, c = j >> 2;
        bsm[tid] = (g == 0 ? bf : g == 1 ? bi : g == 2 ? bg : bo)[c];
    }

    float acc[4][4][4];
#pragma unroll
    for (int a = 0; a < 4; ++a)
#pragma unroll
        for (int b = 0; b < 4; ++b)
#pragma unroll
            for (int q = 0; q < 4; ++q) acc[a][b][q] = 0.0f;

    const int lrow = tid >> 1;
    const int lofs = (tid & 1) * 16;
    const __nv_bfloat16* asrc = g_Ap + (size_t)(m0 + lrow) * KSPLIT + lofs;
    const __nv_bfloat16* bsrc = g_Bp + (size_t)(n0 + lrow) * KSPLIT + lofs;
    const int sidx = lrow * XROWS + lofs;

    const int a_row = wm * 64 + (lane & 7) + ((lane >> 3) & 1) * 8;
    const int a_col = ((lane >> 4) & 1) * 8;
    const int b_row = wn * 32 + (lane & 7) + ((lane >> 4) & 1) * 8;
    const int b_col = ((lane >> 3) & 1) * 8;
    const uint32_t As0 = smem_u32(&As[0][0]);
    const uint32_t Bs0 = smem_u32(&Bs[0][0]);
    const uint32_t BUFA = XBM * XROWS * 2;
    const uint32_t BUFB = XBN * XROWS * 2;

    uint4 a0v = *(const uint4*)(asrc);
    uint4 a1v = *(const uint4*)(asrc + 8);
    uint4 b0v = *(const uint4*)(bsrc);
    uint4 b1v = *(const uint4*)(bsrc + 8);
    *(uint4*)&As[0][sidx]     = a0v;
    *(uint4*)&As[0][sidx + 8] = a1v;
    *(uint4*)&Bs[0][sidx]     = b0v;
    *(uint4*)&Bs[0][sidx + 8] = b1v;
    __syncthreads();

    int p = 0;
    const int NIT = KSPLIT / XBK;   // 48
    for (int it = 0; it < NIT; ++it) {
        const bool more = (it + 1) < NIT;
        if (more) {
            a0v = *(const uint4*)(asrc + (it + 1) * XBK);
            a1v = *(const uint4*)(asrc + (it + 1) * XBK + 8);
            b0v = *(const uint4*)(bsrc + (it + 1) * XBK);
            b1v = *(const uint4*)(bsrc + (it + 1) * XBK + 8);
        }

#pragma unroll
        for (int k16 = 0; k16 < 2; ++k16) {
            uint32_t af[4][4];
#pragma unroll
            for (int mt = 0; mt < 4; ++mt) {
                uint32_t addr = As0 + p * BUFA
                              + (uint32_t)(((a_row + mt * 16) * XROWS + k16 * 16 + a_col) * 2);
                ldsm_x4(af[mt], addr);
            }
            uint32_t bg2[2][4];
#pragma unroll
            for (int hf = 0; hf < 2; ++hf) {
                uint32_t addr = Bs0 + p * BUFB
                              + (uint32_t)(((b_row + hf * 16) * XROWS + k16 * 16 + b_col) * 2);
                ldsm_x4(bg2[hf], addr);
            }
#pragma unroll
            for (int mt = 0; mt < 4; ++mt)
#pragma unroll
                for (int nt = 0; nt < 4; ++nt)
                    hmma16816(acc[mt][nt], af[mt],
                              bg2[nt >> 1][(nt & 1) * 2], bg2[nt >> 1][(nt & 1) * 2 + 1]);
        }

        if (more) {
            *(uint4*)&As[p ^ 1][sidx]     = a0v;
            *(uint4*)&As[p ^ 1][sidx + 8] = a1v;
            *(uint4*)&Bs[p ^ 1][sidx]     = b0v;
            *(uint4*)&Bs[p ^ 1][sidx + 8] = b1v;
            __syncthreads();
        }
        p ^= 1;
    }

#pragma unroll
    for (int mt = 0; mt < 4; ++mt) {
#pragma unroll
        for (int nt = 0; nt < 4; ++nt) {
            int row = m0 + wm * 64 + mt * 16 + (lane >> 2);
            int cl  = wn * 32 + nt * 8 + (lane & 3) * 2;
            float2 v0 = { acc[mt][nt][0] + bsm[cl], acc[mt][nt][1] + bsm[cl + 1] };
            float2 v1 = { acc[mt][nt][2] + bsm[cl], acc[mt][nt][3] + bsm[cl + 1] };
            *(float2*)&g_Xproj[(size_t)row * N4H + n0 + cl]       = v0;
            *(float2*)&g_Xproj[(size_t)(row + 8) * N4H + n0 + cl] = v1;
        }
    }
}

// ---------------- kernel: persistent recurrence (v8, W-stationary smem) -----------
// 128 CTAs x 512 thr. CTA (jg = r>>2, bg = r&3): gate cols [jg*64,+64) (= hidden
// units [jg*16,+16)), batches [bg*16,+16). W slice [512][64] smem (128KB), read
// ONCE per step. h slice [512][16] staged per step (32KB, coalesced L2). Warp w:
// k-slice [w*32,+32); lane (kh = l>>4, cq = l&15): k 16, hidden unit cq (4 gates),
// all 16 batches; 32 ULL accumulators. kh halves shfl-merged; comb[w*16+b][64]
// (conflict-free 256B-contiguous STS; float4 tail reads). Ticket grid barrier.
#define REC_SMEM_BYTES (DIMH*64*4 + DIMH*16*4 + 16*16*64*4)   // 131072+32768+65536 = 229376

__global__ __launch_bounds__(512, 1) void lstm_kernel(
        const float* __restrict__ Wf, const float* __restrict__ Wi,
        const float* __restrict__ Wg, const float* __restrict__ Wo) {
    extern __shared__ float smem[];
    float* Whs  = smem;                              // [512][64]
    float* hs   = smem + DIMH * 64;                  // [512][16]
    float* comb = smem + DIMH * 64 + DIMH * 16;      // [16*16][64]

    const int r    = blockIdx.x;
    const int jg   = r >> 2;            // 0..31 (gate-col group of 64)
    const int bg   = r & 3;             // 0..3  (batch group of 16)
    const int t    = threadIdx.x;
    const int w    = t >> 5;            // 0..15 (k-slice)
    const int lane = t & 31;
    const int kh   = lane >> 4;         // 0/1
    const int cq   = lane & 15;         // hidden unit local
    const int kbase = w * 32 + kh * 16;

    const int tu = t & 15;              // tail: unit local
    const int tb = t >> 4;              // tail: batch local (t<256 -> 0..15)

    // Load W slice once: Whs[k*64 + c], c = hl*4 + gate
    for (int i = t; i < DIMH * 64; i += 512) {
        int k = i >> 6, c = i & 63;
        int gate = c & 3, hl = c >> 2;
        const float* W = (gate == 0) ? Wf : (gate == 1) ? Wi : (gate == 2) ? Wg : Wo;
        Whs[i] = W[(size_t)(DIMD + k) * DIMH + jg * 16 + hl];
    }
    __syncthreads();

    float cst = 0.0f;
    float4 xpA;
    if (t < 256) {
        xpA = __ldg((const float4*)(g_Xproj + (size_t)(bg * 16 + tb) * N4H + jg * 64 + tu * 4));
    }

    for (int step = 0; step < T_STEPS; ++step) {
        if (step > 0) {
            // ---- stage h slice [512][16] (coalesced, L2) ----
            const float* hsrc = g_outT + (size_t)(step - 1) * HB + bg * 16;
#pragma unroll
            for (int rp = 0; rp < 4; ++rp) {
                int idx = t + rp * 512;          // 0..2047 float4 units
                int k = idx >> 2, bq = idx & 3;
                float4 v = __ldcg((const float4*)(hsrc + (size_t)k * BATCH + bq * 4));
                *(float4*)&hs[k * 16 + bq * 4] = v;
            }
            __syncthreads();

            unsigned long long acc[4][8];
#pragma unroll
            for (int i = 0; i < 4; ++i)
#pragma unroll
                for (int j = 0; j < 8; ++j) acc[i][j] = 0ull;

#pragma unroll
            for (int kk = 0; kk < 16; ++kk) {
                const int k = kbase + kk;
                float4 wv = *(const float4*)&Whs[k * 64 + cq * 4];
                ULL2 hp01 = *(const ULL2*)&hs[k * 16];
                ULL2 hp23 = *(const ULL2*)&hs[k * 16 + 4];
                ULL2 hp45 = *(const ULL2*)&hs[k * 16 + 8];
                ULL2 hp67 = *(const ULL2*)&hs[k * 16 + 12];
                unsigned long long hp[8] = { hp01.x, hp01.y, hp23.x, hp23.y,
                                             hp45.x, hp45.y, hp67.x, hp67.y };
                unsigned long long pw[4] = { pack2(wv.x), pack2(wv.y),
                                             pack2(wv.z), pack2(wv.w) };
#pragma unroll
                for (int i = 0; i < 4; ++i)
#pragma unroll
                    for (int j = 0; j < 8; ++j)
                        acc[i][j] = fma2(pw[i], hp[j], acc[i][j]);
            }

            // merge kh halves (xor-symmetric)
#pragma unroll
            for (int i = 0; i < 4; ++i)
#pragma unroll
                for (int j = 0; j < 8; ++j) {
                    unsigned long long o = __shfl_xor_sync(0xffffffffu, acc[i][j], 16);
                    acc[i][j] = add2(acc[i][j], o);
                }

            if (kh == 0) {
                // comb[(w*16 + b)*64 + cq*4 .. +3] = partial for (gate i, unit cq, batch b)
#pragma unroll
                for (int b = 0; b < 16; ++b) {
                    float4 v;
                    v.x = (b & 1) ? hi32(acc[0][b >> 1]) : lo32(acc[0][b >> 1]);
                    v.y = (b & 1) ? hi32(acc[1][b >> 1]) : lo32(acc[1][b >> 1]);
                    v.z = (b & 1) ? hi32(acc[2][b >> 1]) : lo32(acc[2][b >> 1]);
                    v.w = (b & 1) ? hi32(acc[3][b >> 1]) : lo32(acc[3][b >> 1]);
                    *(float4*)&comb[(w * 16 + b) * 64 + cq * 4] = v;
                }
            }
        }
        __syncthreads();

        if (t < 256) {
            float sf = 0.f, si = 0.f, sg = 0.f, so = 0.f;
            if (step > 0) {
#pragma unroll
                for (int ww = 0; ww < 16; ++ww) {
                    float4 p = *(const float4*)&comb[(ww * 16 + tb) * 64 + tu * 4];
                    sf += p.x; si += p.y; sg += p.z; so += p.w;
                }
            }
            float zf = sf + xpA.x, zi = si + xpA.y;
            float zg = sg + xpA.z, zo = so + xpA.w;

            cst = sigf(zf) * cst + sigf(zi) * tanh_(zg);
            float hv = sigf(zo) * tanh_(cst);

            const int hid = jg * 16 + tu;
            const int bglob = bg * 16 + tb;
            g_outT[(size_t)step * HB + hid * BATCH + bglob] = hv;
            if (step == T_STEPS - 1) g_cT[hid * BATCH + bglob] = cst;
            if (step + 1 < T_STEPS) {
                xpA = __ldg((const float4*)(g_Xproj
                        + ((size_t)(step + 1) * BATCH + bglob) * N4H + jg * 64 + tu * 4));
            }
        }

        // ---- monotone ticket grid barrier (proven) ----
        __threadfence();
        __syncthreads();
        if (t == 0) {
            unsigned long long tk = atomicAdd(&g_tick, 1ULL);
            unsigned long long gen = tk >> 7;           // /128 CTAs
            if ((tk & 127ULL) == 127ULL) {
                __threadfence();
                g_rel = gen + 1ULL;
            } else {
                while (g_rel <= gen) { }
                __threadfence();
            }
        }
        __syncthreads();
    }
}

// ---------------- transpose outT -> out (+ hx/cx tail) ----------------------------
__global__ __launch_bounds__(256) void transpose_out(float* __restrict__ out, int out_size) {
    __shared__ float tile[32][65];
    const int tblk = blockIdx.x;
    const int h0   = blockIdx.y * 32;
    const int tx   = threadIdx.x;
    const int ty   = threadIdx.y;
    const int tid  = ty * 64 + tx;
    const int wh   = tid & 31;
    const int wb0  = tid >> 5;

    const size_t tail = (size_t)T_STEPS * BATCH * DIMH;
    const bool write_state = (size_t)out_size >= tail + 2u * BATCH * DIMH;

    if (tblk < T_STEPS) {
        const float* src = g_outT + (size_t)tblk * HB;
#pragma unroll
        for (int i = 0; i < 8; ++i) {
            int hl = i * 4 + ty;
            tile[hl][tx] = src[(size_t)(h0 + hl) * BATCH + tx];
        }
        __syncthreads();
        float* dst = out + (size_t)tblk * BATCH * DIMH;
#pragma unroll
        for (int j = 0; j < 8; ++j) {
            int bb = wb0 + j * 8;
            dst[(size_t)bb * DIMH + h0 + wh] = tile[wh][bb];
        }
    } else if (write_state) {
        const float* src = g_outT + (size_t)(T_STEPS - 1) * HB;
#pragma unroll
        for (int i = 0; i < 8; ++i) {
            int hl = i * 4 + ty;
            tile[hl][tx] = src[(size_t)(h0 + hl) * BATCH + tx];
        }
        __syncthreads();
        float* dst = out + tail;
#pragma unroll
        for (int j = 0; j < 8; ++j) {
            int bb = wb0 + j * 8;
            dst[(size_t)bb * DIMH + h0 + wh] = tile[wh][bb];
        }
        __syncthreads();
#pragma unroll
        for (int i = 0; i < 8; ++i) {
            int hl = i * 4 + ty;
            tile[hl][tx] = g_cT[(size_t)(h0 + hl) * BATCH + tx];
        }
        __syncthreads();
        float* dst2 = out + tail + (size_t)BATCH * DIMH;
#pragma unroll
        for (int j = 0; j < 8; ++j) {
            int bb = wb0 + j * 8;
            dst2[(size_t)bb * DIMH + h0 + wh] = tile[wh][bb];
        }
    }
}

// ---------------- launch ----------------------------------------------------------
extern "C" void kernel_launch(void* const* d_in, const int* in_sizes, int n_in,
                              void* d_out, int out_size) {
    const float* inputs = (const float*)d_in[0];
    const float* Wf = (const float*)d_in[1];
    const float* bf = (const float*)d_in[2];
    const float* Wi = (const float*)d_in[3];
    const float* bi = (const float*)d_in[4];
    const float* Wg = (const float*)d_in[5];
    const float* bg = (const float*)d_in[6];
    const float* Wo = (const float*)d_in[7];
    const float* bo = (const float*)d_in[8];

    pack_a<<<1024, 256>>>(inputs);
    pack_b<<<256, 256>>>(Wf, Wi, Wg, Wo);

    dim3 gx(N4H / XBN, MROWS / XBM);   // (16, 256)
    xproj_mma<<<gx, 256>>>(bf, bi, bg, bo);

    cudaFuncSetAttribute(lstm_kernel, cudaFuncAttributeMaxDynamicSharedMemorySize, REC_SMEM_BYTES);
    lstm_kernel<<<128, 512, REC_SMEM_BYTES>>>(Wf, Wi, Wg, Wo);

    transpose_out<<<dim3(T_STEPS + 1, DIMH / 32), dim3(64, 4)>>>((float*)d_out, out_size);
}

// round 10
// speedup vs baseline: 2.4160x; 1.2610x over previous
#include <cuda_runtime.h>
#include <cuda_bf16.h>
#include <cstdint>
#include <cstddef>

#define T_STEPS 512
#define BATCH   64
#define DIMD    512
#define DIMH    512
#define N4H     2048   // 4 gates * H, packed as j' = hid*4 + gate
#define KDIM    512
#define HB      (DIMH * BATCH)      // 32768
#define MROWS   (T_STEPS * BATCH)   // 32768
#define KSPLIT  1536                // 3 * 512 (bf16x3 split segments)

// ---------------- device scratch (static) ----------------------------------------
__device__ float g_Xproj[(size_t)T_STEPS * BATCH * N4H];   // 256 MB [t*B+b][j']
__device__ unsigned g_hx[(size_t)T_STEPS * HB];            // 64 MB [t][b][hid] packed (hi|lo) bf16
__device__ unsigned g_cx[HB];                              // final c packed [b][hid]
__device__ __nv_bfloat16 g_Ap[(size_t)MROWS * KSPLIT];     // 96 MB  A' = [hi | lo | hi]
__device__ __nv_bfloat16 g_Bp[(size_t)N4H * KSPLIT];       // 6 MB   B'[j'][k] = [hi | hi | lo]
__device__ __nv_bfloat16 g_Whh[(size_t)N4H * KDIM];        // 2 MB   Wh^T hi [j'][k]
__device__ __nv_bfloat16 g_Whl[(size_t)N4H * KDIM];        // 2 MB   Wh^T lo [j'][k]
__device__ unsigned long long g_tickd[4 * 16];             // per-domain monotone tickets (128B apart)
__device__ volatile unsigned long long g_reld[4 * 16];     // per-domain releases

// ---------------- helpers ----------------------------------------------------------
static __device__ __forceinline__ float sigf(float x) {
    return __fdividef(1.0f, 1.0f + __expf(-x));
}
static __device__ __forceinline__ float tanh_(float x) {
    return 2.0f * sigf(2.0f * x) - 1.0f;
}
static __device__ __forceinline__ unsigned pack_hl(float v) {
    __nv_bfloat16 hb = __float2bfloat16(v);
    __nv_bfloat16 lb = __float2bfloat16(v - __bfloat162float(hb));
    return (unsigned)__bfloat16_as_ushort(hb) | ((unsigned)__bfloat16_as_ushort(lb) << 16);
}
static __device__ __forceinline__ float unpack_hl(unsigned u) {
    return __bfloat162float(__ushort_as_bfloat16((unsigned short)(u & 0xffffu)))
         + __bfloat162float(__ushort_as_bfloat16((unsigned short)(u >> 16)));
}
static __device__ __forceinline__ uint32_t smem_u32(const void* p) {
    uint32_t a;
    asm("{ .reg .u64 t; cvta.to.shared.u64 t, %1; cvt.u32.u64 %0, t; }" : "=r"(a) : "l"(p));
    return a;
}
static __device__ __forceinline__ void ldsm_x4(uint32_t* r, uint32_t addr) {
    asm volatile("ldmatrix.sync.aligned.m8n8.x4.shared.b16 {%0,%1,%2,%3}, [%4];"
                 : "=r"(r[0]), "=r"(r[1]), "=r"(r[2]), "=r"(r[3]) : "r"(addr));
}
static __device__ __forceinline__ void hmma16816(float* c, const uint32_t* a,
                                                 uint32_t b0, uint32_t b1) {
    asm volatile("mma.sync.aligned.m16n8k16.row.col.f32.bf16.bf16.f32 "
                 "{%0,%1,%2,%3}, {%4,%5,%6,%7}, {%8,%9}, {%0,%1,%2,%3};"
                 : "+f"(c[0]), "+f"(c[1]), "+f"(c[2]), "+f"(c[3])
                 : "r"(a[0]), "r"(a[1]), "r"(a[2]), "r"(a[3]), "r"(b0), "r"(b1));
}

// ---------------- pack kernels (bf16 hi/lo split) ---------------------------------
__global__ void pack_a(const float* __restrict__ X) {
    size_t idx = (size_t)blockIdx.x * blockDim.x + threadIdx.x;
    size_t stride = (size_t)gridDim.x * blockDim.x;
    for (size_t i = idx; i < (size_t)MROWS * KDIM; i += stride) {
        size_t m = i / KDIM, k = i % KDIM;
        float x = X[i];
        __nv_bfloat16 hi = __float2bfloat16(x);
        __nv_bfloat16 lo = __float2bfloat16(x - __bfloat162float(hi));
        __nv_bfloat16* row = g_Ap + m * KSPLIT;
        row[k] = hi; row[512 + k] = lo; row[1024 + k] = hi;
    }
}
__global__ void pack_b(const float* __restrict__ Wf, const float* __restrict__ Wi,
                       const float* __restrict__ Wg, const float* __restrict__ Wo) {
    size_t idx = (size_t)blockIdx.x * blockDim.x + threadIdx.x;
    size_t stride = (size_t)gridDim.x * blockDim.x;
    for (size_t i = idx; i < (size_t)N4H * KDIM; i += stride) {
        size_t j = i / KDIM, k = i % KDIM;
        int g = (int)(j & 3), c = (int)(j >> 2);
        const float* W = (g == 0) ? Wf : (g == 1) ? Wi : (g == 2) ? Wg : Wo;
        // x-part (rows 0..511)
        float w = W[k * DIMH + c];
        __nv_bfloat16 hi = __float2bfloat16(w);
        __nv_bfloat16 lo = __float2bfloat16(w - __bfloat162float(hi));
        __nv_bfloat16* row = g_Bp + j * KSPLIT;
        row[k] = hi; row[512 + k] = hi; row[1024 + k] = lo;
        // h-part (rows 512..1023)
        float wh = W[(size_t)(DIMD + k) * DIMH + c];
        __nv_bfloat16 hh = __float2bfloat16(wh);
        __nv_bfloat16 hl = __float2bfloat16(wh - __bfloat162float(hh));
        g_Whh[j * KDIM + k] = hh;
        g_Whl[j * KDIM + k] = hl;
    }
}

// ---------------- kernel: xproj GEMM via mma.sync (bf16x3, fp32 accum) ------------
#define XBM 128
#define XBN 128
#define XBK 32
#define XROWS 40

__global__ __launch_bounds__(256) void xproj_mma(
        const float* __restrict__ bf, const float* __restrict__ bi,
        const float* __restrict__ bg, const float* __restrict__ bo) {
    __shared__ __nv_bfloat16 As[2][XBM * XROWS];
    __shared__ __nv_bfloat16 Bs[2][XBN * XROWS];
    __shared__ float bsm[XBN];

    const int tid  = threadIdx.x;
    const int lane = tid & 31;
    const int wid  = tid >> 5;
    const int wm   = wid & 1;
    const int wn   = wid >> 1;
    const int m0   = blockIdx.y * XBM;
    const int n0   = blockIdx.x * XBN;

    if (tid < XBN) {
        int j = n0 + tid, g = j & 3, c = j >> 2;
        bsm[tid] = (g == 0 ? bf : g == 1 ? bi : g == 2 ? bg : bo)[c];
    }

    float acc[4][4][4];
#pragma unroll
    for (int a = 0; a < 4; ++a)
#pragma unroll
        for (int b = 0; b < 4; ++b)
#pragma unroll
            for (int q = 0; q < 4; ++q) acc[a][b][q] = 0.0f;

    const int lrow = tid >> 1;
    const int lofs = (tid & 1) * 16;
    const __nv_bfloat16* asrc = g_Ap + (size_t)(m0 + lrow) * KSPLIT + lofs;
    const __nv_bfloat16* bsrc = g_Bp + (size_t)(n0 + lrow) * KSPLIT + lofs;
    const int sidx = lrow * XROWS + lofs;

    const int a_row = wm * 64 + (lane & 7) + ((lane >> 3) & 1) * 8;
    const int a_col = ((lane >> 4) & 1) * 8;
    const int b_row = wn * 32 + (lane & 7) + ((lane >> 4) & 1) * 8;
    const int b_col = ((lane >> 3) & 1) * 8;
    const uint32_t As0 = smem_u32(&As[0][0]);
    const uint32_t Bs0 = smem_u32(&Bs[0][0]);
    const uint32_t BUFA = XBM * XROWS * 2;
    const uint32_t BUFB = XBN * XROWS * 2;

    uint4 a0v = *(const uint4*)(asrc);
    uint4 a1v = *(const uint4*)(asrc + 8);
    uint4 b0v = *(const uint4*)(bsrc);
    uint4 b1v = *(const uint4*)(bsrc + 8);
    *(uint4*)&As[0][sidx]     = a0v;
    *(uint4*)&As[0][sidx + 8] = a1v;
    *(uint4*)&Bs[0][sidx]     = b0v;
    *(uint4*)&Bs[0][sidx + 8] = b1v;
    __syncthreads();

    int p = 0;
    const int NIT = KSPLIT / XBK;   // 48
    for (int it = 0; it < NIT; ++it) {
        const bool more = (it + 1) < NIT;
        if (more) {
            a0v = *(const uint4*)(asrc + (it + 1) * XBK);
            a1v = *(const uint4*)(asrc + (it + 1) * XBK + 8);
            b0v = *(const uint4*)(bsrc + (it + 1) * XBK);
            b1v = *(const uint4*)(bsrc + (it + 1) * XBK + 8);
        }

#pragma unroll
        for (int k16 = 0; k16 < 2; ++k16) {
            uint32_t af[4][4];
#pragma unroll
            for (int mt = 0; mt < 4; ++mt) {
                uint32_t addr = As0 + p * BUFA
                              + (uint32_t)(((a_row + mt * 16) * XROWS + k16 * 16 + a_col) * 2);
                ldsm_x4(af[mt], addr);
            }
            uint32_t bg2[2][4];
#pragma unroll
            for (int hf = 0; hf < 2; ++hf) {
                uint32_t addr = Bs0 + p * BUFB
                              + (uint32_t)(((b_row + hf * 16) * XROWS + k16 * 16 + b_col) * 2);
                ldsm_x4(bg2[hf], addr);
            }
#pragma unroll
            for (int mt = 0; mt < 4; ++mt)
#pragma unroll
                for (int nt = 0; nt < 4; ++nt)
                    hmma16816(acc[mt][nt], af[mt],
                              bg2[nt >> 1][(nt & 1) * 2], bg2[nt >> 1][(nt & 1) * 2 + 1]);
        }

        if (more) {
            *(uint4*)&As[p ^ 1][sidx]     = a0v;
            *(uint4*)&As[p ^ 1][sidx + 8] = a1v;
            *(uint4*)&Bs[p ^ 1][sidx]     = b0v;
            *(uint4*)&Bs[p ^ 1][sidx + 8] = b1v;
            __syncthreads();
        }
        p ^= 1;
    }

#pragma unroll
    for (int mt = 0; mt < 4; ++mt) {
#pragma unroll
        for (int nt = 0; nt < 4; ++nt) {
            int row = m0 + wm * 64 + mt * 16 + (lane >> 2);
            int cl  = wn * 32 + nt * 8 + (lane & 3) * 2;
            float2 v0 = { acc[mt][nt][0] + bsm[cl], acc[mt][nt][1] + bsm[cl + 1] };
            float2 v1 = { acc[mt][nt][2] + bsm[cl], acc[mt][nt][3] + bsm[cl + 1] };
            *(float2*)&g_Xproj[(size_t)row * N4H + n0 + cl]       = v0;
            *(float2*)&g_Xproj[(size_t)(row + 8) * N4H + n0 + cl] = v1;
        }
    }
}

// ---------------- kernel: persistent recurrence via mma.sync (v9) -----------------
// 128 CTAs x 256 thr. CTA r: jg = r&31 (gate cols [jg*64,+64) = hid [jg*16,+16)),
// bg = r>>5 (batches [bg*16,+16)). 4 independent 32-CTA barrier domains (per bg).
// h stored packed bf16 (hi|lo) in g_hx[t][b][hid]. Per step: stage A tiles (16x512
// hi/lo), 3-pass HMMA (Ahi*Whi + Alo*Whi + Ahi*Wlo), fp32 frags, epilogue gates.
#define LS_W 520   // smem row stride (512 + 8 pad) in bf16
#define LSTM_SMEM_BYTES ((2*64*LS_W + 2*16*LS_W) * 2 + 2*256*4)   // 166400 + 2048

__global__ __launch_bounds__(256, 1) void lstm_mma() {
    extern __shared__ __nv_bfloat16 sm[];
    __nv_bfloat16* Wh = sm;                    // [64][LS_W]
    __nv_bfloat16* Wl = Wh + 64 * LS_W;
    __nv_bfloat16* Ah = Wl + 64 * LS_W;        // [16][LS_W]
    __nv_bfloat16* Al = Ah + 16 * LS_W;
    unsigned* htile = (unsigned*)(Al + 16 * LS_W);   // [16*16]
    unsigned* ctile = htile + 256;

    const int r    = blockIdx.x;
    const int jg   = r & 31;
    const int bg   = r >> 5;
    const int t    = threadIdx.x;
    const int w    = t >> 5;       // 0..7: n8 tile (cols [w*8,+8))
    const int lane = t & 31;

    // stage W^T hi/lo slices once (64 rows x 512 bf16 each)
    for (int idx = t; idx < 64 * 64; idx += 256) {
        int row = idx >> 6, ch = idx & 63;
        uint4 vh = *(const uint4*)&g_Whh[(size_t)(jg * 64 + row) * KDIM + ch * 8];
        uint4 vl = *(const uint4*)&g_Whl[(size_t)(jg * 64 + row) * KDIM + ch * 8];
        *(uint4*)&Wh[row * LS_W + ch * 8] = vh;
        *(uint4*)&Wl[row * LS_W + ch * 8] = vl;
    }
    __syncthreads();

    // per-lane output assignment
    const int sel   = (lane & 3) >> 1;            // hid within warp pair
    const int hidl  = w * 2 + sel;                // 0..15
    const int b_l   = (lane >> 2) + (lane & 1) * 8;  // 0..15
    const int hid_g = jg * 16 + hidl;
    const int b_g   = bg * 16 + b_l;

    // ldsm element offsets (bf16 units)
    const uint32_t Ah0 = smem_u32(Ah), Al0 = smem_u32(Al);
    const uint32_t Wh0 = smem_u32(Wh), Wl0 = smem_u32(Wl);
    const uint32_t aoff = (uint32_t)((((lane & 7) + ((lane >> 3) & 1) * 8) * LS_W
                                      + ((lane >> 4) & 1) * 8) * 2);
    const uint32_t boff = (uint32_t)((((w >> 1) * 16 + (lane & 7) + ((lane >> 4) & 1) * 8) * LS_W
                                      + ((lane >> 3) & 1) * 8) * 2);
    const int fb = (w & 1) * 2;    // B frag pair selector

    float cst = 0.0f;
    float4 xp = __ldg((const float4*)(g_Xproj + (size_t)b_g * N4H + hid_g * 4));

    for (int step = 0; step < T_STEPS; ++step) {
        float s0 = 0.f, s1 = 0.f, s2 = 0.f, s3 = 0.f;

        if (step > 0) {
            // ---- stage A (hi/lo): warp w stages batch rows w*2, w*2+1 ----
            const unsigned* src = g_hx + (size_t)(step - 1) * HB + (size_t)(bg * 16) * DIMH;
#pragma unroll
            for (int bb = 0; bb < 2; ++bb) {
                int brow = w * 2 + bb;
#pragma unroll
                for (int q = 0; q < 4; ++q) {
                    uint4 v = __ldcg((const uint4*)(src + (size_t)brow * DIMH + q * 128 + lane * 4));
                    uint2 hhv, llv;
                    hhv.x = (v.x & 0xffffu) | (v.y << 16);
                    hhv.y = (v.z & 0xffffu) | (v.w << 16);
                    llv.x = (v.x >> 16) | (v.y & 0xffff0000u);
                    llv.y = (v.z >> 16) | (v.w & 0xffff0000u);
                    *(uint2*)&Ah[brow * LS_W + q * 128 + lane * 4] = hhv;
                    *(uint2*)&Al[brow * LS_W + q * 128 + lane * 4] = llv;
                }
            }
            __syncthreads();

            // ---- 3-pass HMMA over K=512 (32 ksteps) ----
            float acc[3][4];
#pragma unroll
            for (int p = 0; p < 3; ++p)
#pragma unroll
                for (int q = 0; q < 4; ++q) acc[p][q] = 0.0f;

#pragma unroll
            for (int ks = 0; ks < 32; ++ks) {
                const uint32_t kofs = (uint32_t)(ks * 16 * 2);
                uint32_t afh[4], afl[4], bh[4], bl[4];
                ldsm_x4(afh, Ah0 + aoff + kofs);
                ldsm_x4(afl, Al0 + aoff + kofs);
                ldsm_x4(bh,  Wh0 + boff + kofs);
                ldsm_x4(bl,  Wl0 + boff + kofs);
                hmma16816(acc[0], afh, bh[fb], bh[fb + 1]);
                hmma16816(acc[1], afl, bh[fb], bh[fb + 1]);
                hmma16816(acc[2], afh, bl[fb], bl[fb + 1]);
            }
            s0 = acc[0][0] + acc[1][0] + acc[2][0];
            s1 = acc[0][1] + acc[1][1] + acc[2][1];
            s2 = acc[0][2] + acc[1][2] + acc[2][2];
            s3 = acc[0][3] + acc[1][3] + acc[2][3];
        }

        // ---- gate combine: partner lane (xor 1) holds the other gate pair ----
        float e0 = __shfl_xor_sync(0xffffffffu, s0, 1);
        float e1 = __shfl_xor_sync(0xffffffffu, s1, 1);
        float e2 = __shfl_xor_sync(0xffffffffu, s2, 1);
        float e3 = __shfl_xor_sync(0xffffffffu, s3, 1);
        const bool odd = (lane & 1);
        float zf = (odd ? e2 : s0) + xp.x;
        float zi = (odd ? e3 : s1) + xp.y;
        float zg = (odd ? s2 : e0) + xp.z;
        float zo = (odd ? s3 : e1) + xp.w;

        cst = sigf(zf) * cst + sigf(zi) * tanh_(zg);
        float hv = sigf(zo) * tanh_(cst);

        htile[b_l * 16 + hidl] = pack_hl(hv);
        if (step == T_STEPS - 1) ctile[b_l * 16 + hidl] = pack_hl(cst);

        // prefetch next step's xproj (hidden behind epilogue + barrier)
        if (step + 1 < T_STEPS)
            xp = __ldg((const float4*)(g_Xproj
                    + ((size_t)(step + 1) * BATCH + b_g) * N4H + hid_g * 4));

        __syncthreads();
        // coalesced h' store: thread t -> (b = t>>4, hid = t&15)
        g_hx[(size_t)step * HB + (size_t)(bg * 16 + (t >> 4)) * DIMH + jg * 16 + (t & 15)]
            = htile[t];
        if (step == T_STEPS - 1)
            g_cx[(size_t)(bg * 16 + (t >> 4)) * DIMH + jg * 16 + (t & 15)] = ctile[t];

        // ---- per-domain ticket barrier (32 CTAs) ----
        __threadfence();
        __syncthreads();
        if (t == 0) {
            unsigned long long tk = atomicAdd(&g_tickd[bg * 16], 1ULL);
            unsigned long long gen = tk >> 5;
            if ((tk & 31ULL) == 31ULL) {
                __threadfence();
                g_reld[bg * 16] = gen + 1ULL;
            } else {
                while (g_reld[bg * 16] <= gen) { }
                __threadfence();
            }
        }
        __syncthreads();
    }
}

// ---------------- kernel: emit final output (unpack bf16 hi/lo -> fp32) ----------
__global__ __launch_bounds__(512) void emit_out(float* __restrict__ out, int out_size) {
    const int bx = blockIdx.x;        // 0..511: step t; 512: hx tail; 513: cx tail
    const int i4 = blockIdx.y * 512 + threadIdx.x;   // uint4 index within HB/4
    const size_t tail = (size_t)T_STEPS * HB;
    const bool write_state = (size_t)out_size >= tail + 2u * HB;

    const unsigned* src;
    float* dst;
    if (bx < T_STEPS) {
        src = g_hx + (size_t)bx * HB;
        dst = out + (size_t)bx * HB;
    } else if (bx == T_STEPS) {
        if (!write_state) return;
        src = g_hx + (size_t)(T_STEPS - 1) * HB;
        dst = out + tail;
    } else {
        if (!write_state) return;
        src = g_cx;
        dst = out + tail + HB;
    }
    uint4 v = *(const uint4*)(src + (size_t)i4 * 4);
    float4 o;
    o.x = unpack_hl(v.x);
    o.y = unpack_hl(v.y);
    o.z = unpack_hl(v.z);
    o.w = unpack_hl(v.w);
    *(float4*)(dst + (size_t)i4 * 4) = o;
}

// ---------------- launch ----------------------------------------------------------
extern "C" void kernel_launch(void* const* d_in, const int* in_sizes, int n_in,
                              void* d_out, int out_size) {
    const float* inputs = (const float*)d_in[0];
    const float* Wf = (const float*)d_in[1];
    const float* bf = (const float*)d_in[2];
    const float* Wi = (const float*)d_in[3];
    const float* bi = (const float*)d_in[4];
    const float* Wg = (const float*)d_in[5];
    const float* bg = (const float*)d_in[6];
    const float* Wo = (const float*)d_in[7];
    const float* bo = (const float*)d_in[8];

    pack_a<<<1024, 256>>>(inputs);
    pack_b<<<256, 256>>>(Wf, Wi, Wg, Wo);

    dim3 gx(N4H / XBN, MROWS / XBM);   // (16, 256)
    xproj_mma<<<gx, 256>>>(bf, bi, bg, bo);

    cudaFuncSetAttribute(lstm_mma, cudaFuncAttributeMaxDynamicSharedMemorySize, LSTM_SMEM_BYTES);
    lstm_mma<<<128, 256, LSTM_SMEM_BYTES>>>();

    emit_out<<<dim3(T_STEPS + 2, HB / 2048), 512>>>((float*)d_out, out_size);
}

// round 11
// speedup vs baseline: 2.7872x; 1.1536x over previous
#include <cuda_runtime.h>
#include <cuda_bf16.h>
#include <cstdint>
#include <cstddef>

#define T_STEPS 512
#define BATCH   64
#define DIMD    512
#define DIMH    512
#define N4H     2048   // 4 gates * H, packed as j' = hid*4 + gate
#define KDIM    512
#define HB      (DIMH * BATCH)      // 32768
#define MROWS   (T_STEPS * BATCH)   // 32768
#define KSPLIT  1536                // 3 * 512 (bf16x3 split segments)

// ---------------- device scratch (static) ----------------------------------------
__device__ float g_Xproj[(size_t)T_STEPS * BATCH * N4H];   // 256 MB [t*B+b][j']
__device__ unsigned g_hx[(size_t)T_STEPS * HB];            // 64 MB [t][b][hid] packed (hi|lo)
__device__ unsigned g_cx[HB];                              // final c packed [b][hid]
__device__ __nv_bfloat16 g_Ap[(size_t)MROWS * KSPLIT];     // 96 MB  A' = [hi | lo | hi]
__device__ __nv_bfloat16 g_Bp[(size_t)N4H * KSPLIT];       // 6 MB   B'[j'][k] = [hi | hi | lo]
__device__ __nv_bfloat16 g_Whh[(size_t)N4H * KDIM];        // 2 MB   Wh^T hi [j'][k]
__device__ __nv_bfloat16 g_Whl[(size_t)N4H * KDIM];        // 2 MB   Wh^T lo [j'][k]
__device__ unsigned long long g_tickd[4 * 16];             // per-domain tickets (128B apart)
__device__ volatile unsigned long long g_reld[4 * 16];     // per-domain releases

// ---------------- helpers ----------------------------------------------------------
static __device__ __forceinline__ float sigf(float x) {
    return __fdividef(1.0f, 1.0f + __expf(-x));
}
static __device__ __forceinline__ float tanh_(float x) {
    return 2.0f * sigf(2.0f * x) - 1.0f;
}
static __device__ __forceinline__ unsigned pack_hl(float v) {
    __nv_bfloat16 hb = __float2bfloat16(v);
    __nv_bfloat16 lb = __float2bfloat16(v - __bfloat162float(hb));
    return (unsigned)__bfloat16_as_ushort(hb) | ((unsigned)__bfloat16_as_ushort(lb) << 16);
}
static __device__ __forceinline__ float unpack_hl(unsigned u) {
    return __bfloat162float(__ushort_as_bfloat16((unsigned short)(u & 0xffffu)))
         + __bfloat162float(__ushort_as_bfloat16((unsigned short)(u >> 16)));
}
static __device__ __forceinline__ uint32_t smem_u32(const void* p) {
    uint32_t a;
    asm("{ .reg .u64 t; cvta.to.shared.u64 t, %1; cvt.u32.u64 %0, t; }" : "=r"(a) : "l"(p));
    return a;
}
static __device__ __forceinline__ void ldsm_x4(uint32_t* r, uint32_t addr) {
    asm volatile("ldmatrix.sync.aligned.m8n8.x4.shared.b16 {%0,%1,%2,%3}, [%4];"
                 : "=r"(r[0]), "=r"(r[1]), "=r"(r[2]), "=r"(r[3]) : "r"(addr));
}
static __device__ __forceinline__ void hmma16816(float* c, const uint32_t* a,
                                                 uint32_t b0, uint32_t b1) {
    asm volatile("mma.sync.aligned.m16n8k16.row.col.f32.bf16.bf16.f32 "
                 "{%0,%1,%2,%3}, {%4,%5,%6,%7}, {%8,%9}, {%0,%1,%2,%3};"
                 : "+f"(c[0]), "+f"(c[1]), "+f"(c[2]), "+f"(c[3])
                 : "r"(a[0]), "r"(a[1]), "r"(a[2]), "r"(a[3]), "r"(b0), "r"(b1));
}

// ---------------- pack kernels (bf16 hi/lo split) ---------------------------------
__global__ void pack_a(const float* __restrict__ X) {
    size_t idx = (size_t)blockIdx.x * blockDim.x + threadIdx.x;
    size_t stride = (size_t)gridDim.x * blockDim.x;
    for (size_t i = idx; i < (size_t)MROWS * KDIM; i += stride) {
        size_t m = i / KDIM, k = i % KDIM;
        float x = X[i];
        __nv_bfloat16 hi = __float2bfloat16(x);
        __nv_bfloat16 lo = __float2bfloat16(x - __bfloat162float(hi));
        __nv_bfloat16* row = g_Ap + m * KSPLIT;
        row[k] = hi; row[512 + k] = lo; row[1024 + k] = hi;
    }
}
__global__ void pack_b(const float* __restrict__ Wf, const float* __restrict__ Wi,
                       const float* __restrict__ Wg, const float* __restrict__ Wo) {
    size_t idx = (size_t)blockIdx.x * blockDim.x + threadIdx.x;
    size_t stride = (size_t)gridDim.x * blockDim.x;
    for (size_t i = idx; i < (size_t)N4H * KDIM; i += stride) {
        size_t j = i / KDIM, k = i % KDIM;
        int g = (int)(j & 3), c = (int)(j >> 2);
        const float* W = (g == 0) ? Wf : (g == 1) ? Wi : (g == 2) ? Wg : Wo;
        float w = W[k * DIMH + c];
        __nv_bfloat16 hi = __float2bfloat16(w);
        __nv_bfloat16 lo = __float2bfloat16(w - __bfloat162float(hi));
        __nv_bfloat16* row = g_Bp + j * KSPLIT;
        row[k] = hi; row[512 + k] = hi; row[1024 + k] = lo;
        float wh = W[(size_t)(DIMD + k) * DIMH + c];
        __nv_bfloat16 hh = __float2bfloat16(wh);
        __nv_bfloat16 hl = __float2bfloat16(wh - __bfloat162float(hh));
        g_Whh[j * KDIM + k] = hh;
        g_Whl[j * KDIM + k] = hl;
    }
}

// ---------------- kernel: xproj GEMM via mma.sync (bf16x3, fp32 accum) ------------
#define XBM 128
#define XBN 128
#define XBK 32
#define XROWS 40

__global__ __launch_bounds__(256) void xproj_mma(
        const float* __restrict__ bf, const float* __restrict__ bi,
        const float* __restrict__ bg, const float* __restrict__ bo) {
    __shared__ __nv_bfloat16 As[2][XBM * XROWS];
    __shared__ __nv_bfloat16 Bs[2][XBN * XROWS];
    __shared__ float bsm[XBN];

    const int tid  = threadIdx.x;
    const int lane = tid & 31;
    const int wid  = tid >> 5;
    const int wm   = wid & 1;
    const int wn   = wid >> 1;
    const int m0   = blockIdx.y * XBM;
    const int n0   = blockIdx.x * XBN;

    if (tid < XBN) {
        int j = n0 + tid, g = j & 3, c = j >> 2;
        bsm[tid] = (g == 0 ? bf : g == 1 ? bi : g == 2 ? bg : bo)[c];
    }

    float acc[4][4][4];
#pragma unroll
    for (int a = 0; a < 4; ++a)
#pragma unroll
        for (int b = 0; b < 4; ++b)
#pragma unroll
            for (int q = 0; q < 4; ++q) acc[a][b][q] = 0.0f;

    const int lrow = tid >> 1;
    const int lofs = (tid & 1) * 16;
    const __nv_bfloat16* asrc = g_Ap + (size_t)(m0 + lrow) * KSPLIT + lofs;
    const __nv_bfloat16* bsrc = g_Bp + (size_t)(n0 + lrow) * KSPLIT + lofs;
    const int sidx = lrow * XROWS + lofs;

    const int a_row = wm * 64 + (lane & 7) + ((lane >> 3) & 1) * 8;
    const int a_col = ((lane >> 4) & 1) * 8;
    const int b_row = wn * 32 + (lane & 7) + ((lane >> 4) & 1) * 8;
    const int b_col = ((lane >> 3) & 1) * 8;
    const uint32_t As0 = smem_u32(&As[0][0]);
    const uint32_t Bs0 = smem_u32(&Bs[0][0]);
    const uint32_t BUFA = XBM * XROWS * 2;
    const uint32_t BUFB = XBN * XROWS * 2;

    uint4 a0v = *(const uint4*)(asrc);
    uint4 a1v = *(const uint4*)(asrc + 8);
    uint4 b0v = *(const uint4*)(bsrc);
    uint4 b1v = *(const uint4*)(bsrc + 8);
    *(uint4*)&As[0][sidx]     = a0v;
    *(uint4*)&As[0][sidx + 8] = a1v;
    *(uint4*)&Bs[0][sidx]     = b0v;
    *(uint4*)&Bs[0][sidx + 8] = b1v;
    __syncthreads();

    int p = 0;
    const int NIT = KSPLIT / XBK;   // 48
    for (int it = 0; it < NIT; ++it) {
        const bool more = (it + 1) < NIT;
        if (more) {
            a0v = *(const uint4*)(asrc + (it + 1) * XBK);
            a1v = *(const uint4*)(asrc + (it + 1) * XBK + 8);
            b0v = *(const uint4*)(bsrc + (it + 1) * XBK);
            b1v = *(const uint4*)(bsrc + (it + 1) * XBK + 8);
        }

#pragma unroll
        for (int k16 = 0; k16 < 2; ++k16) {
            uint32_t af[4][4];
#pragma unroll
            for (int mt = 0; mt < 4; ++mt) {
                uint32_t addr = As0 + p * BUFA
                              + (uint32_t)(((a_row + mt * 16) * XROWS + k16 * 16 + a_col) * 2);
                ldsm_x4(af[mt], addr);
            }
            uint32_t bg2[2][4];
#pragma unroll
            for (int hf = 0; hf < 2; ++hf) {
                uint32_t addr = Bs0 + p * BUFB
                              + (uint32_t)(((b_row + hf * 16) * XROWS + k16 * 16 + b_col) * 2);
                ldsm_x4(bg2[hf], addr);
            }
#pragma unroll
            for (int mt = 0; mt < 4; ++mt)
#pragma unroll
                for (int nt = 0; nt < 4; ++nt)
                    hmma16816(acc[mt][nt], af[mt],
                              bg2[nt >> 1][(nt & 1) * 2], bg2[nt >> 1][(nt & 1) * 2 + 1]);
        }

        if (more) {
            *(uint4*)&As[p ^ 1][sidx]     = a0v;
            *(uint4*)&As[p ^ 1][sidx + 8] = a1v;
            *(uint4*)&Bs[p ^ 1][sidx]     = b0v;
            *(uint4*)&Bs[p ^ 1][sidx + 8] = b1v;
            __syncthreads();
        }
        p ^= 1;
    }

#pragma unroll
    for (int mt = 0; mt < 4; ++mt) {
#pragma unroll
        for (int nt = 0; nt < 4; ++nt) {
            int row = m0 + wm * 64 + mt * 16 + (lane >> 2);
            int cl  = wn * 32 + nt * 8 + (lane & 3) * 2;
            float2 v0 = { acc[mt][nt][0] + bsm[cl], acc[mt][nt][1] + bsm[cl + 1] };
            float2 v1 = { acc[mt][nt][2] + bsm[cl], acc[mt][nt][3] + bsm[cl + 1] };
            *(float2*)&g_Xproj[(size_t)row * N4H + n0 + cl]       = v0;
            *(float2*)&g_Xproj[(size_t)(row + 8) * N4H + n0 + cl] = v1;
        }
    }
}

// ---------------- kernel: persistent recurrence via mma.sync (v10) ----------------
// 128 CTAs x 256 thr. CTA r: jg = r&31 (cols [jg*64,+64) = hid [jg*16,+16)),
// bg = r>>5 (batches [bg*16,+16)); 4 independent 32-CTA barrier domains.
// Warp w: kh = w>>2 (K half of 256), wn = w&3 (cols [wn*16,+16)). Per kstep:
// 4 ldsm.x4 (Ah,Al,Wh,Wl; ALL frags used) + 6 HMMA. K halves reduced via smem.
#define LS_W 520   // smem row stride (512 + 8 pad) in bf16
#define RED_OFF (2*64*LS_W + 2*16*LS_W)                       // bf16 units
#define LSTM_SMEM_BYTES (RED_OFF * 2 + 4*32*8*4 + 2*256*4)    // 166400+4096+2048

__global__ __launch_bounds__(256, 1) void lstm_mma() {
    extern __shared__ __nv_bfloat16 sm[];
    __nv_bfloat16* Wh = sm;                    // [64][LS_W]
    __nv_bfloat16* Wl = Wh + 64 * LS_W;
    __nv_bfloat16* Ah = Wl + 64 * LS_W;        // [16][LS_W]
    __nv_bfloat16* Al = Ah + 16 * LS_W;
    float* red = (float*)(sm + RED_OFF);       // [4*32][8]
    unsigned* htile = (unsigned*)(red + 4 * 32 * 8);   // [256]
    unsigned* ctile = htile + 256;

    const int r    = blockIdx.x;
    const int jg   = r & 31;
    const int bg   = r >> 5;
    const int t    = threadIdx.x;
    const int w    = t >> 5;
    const int lane = t & 31;
    const int kh   = w >> 2;        // K half
    const int wn   = w & 3;         // col group of 16

    // stage W^T hi/lo slices once (64 rows x 512 bf16 each)
    for (int idx = t; idx < 64 * 64; idx += 256) {
        int row = idx >> 6, ch = idx & 63;
        uint4 vh = *(const uint4*)&g_Whh[(size_t)(jg * 64 + row) * KDIM + ch * 8];
        uint4 vl = *(const uint4*)&g_Whl[(size_t)(jg * 64 + row) * KDIM + ch * 8];
        *(uint4*)&Wh[row * LS_W + ch * 8] = vh;
        *(uint4*)&Wl[row * LS_W + ch * 8] = vl;
    }
    __syncthreads();

    // ldsm element offsets (validated layout from R10)
    const uint32_t Ah0 = smem_u32(Ah), Al0 = smem_u32(Al);
    const uint32_t Wh0 = smem_u32(Wh), Wl0 = smem_u32(Wl);
    const int kbase = kh * 256;
    const uint32_t aoff = (uint32_t)((((lane & 7) + ((lane >> 3) & 1) * 8) * LS_W
                                      + kbase + ((lane >> 4) & 1) * 8) * 2);
    const uint32_t boff = (uint32_t)(((wn * 16 + (lane & 7) + ((lane >> 4) & 1) * 8) * LS_W
                                      + kbase + ((lane >> 3) & 1) * 8) * 2);

    // epilogue assignment (warps 0-3): 2 outputs per lane
    const int qq    = (lane & 3) >> 1;
    const int odd   = lane & 1;
    const int b_l   = (lane >> 2) + odd * 8;
    const int hidA  = wn * 4 + qq;       // from n8#0
    const int hidB  = wn * 4 + 2 + qq;   // from n8#1
    const int b_g   = bg * 16 + b_l;

    float cstA = 0.0f, cstB = 0.0f;
    float4 xpA, xpB;
    if (w < 4) {
        xpA = __ldg((const float4*)(g_Xproj + (size_t)b_g * N4H + (jg * 16 + hidA) * 4));
        xpB = __ldg((const float4*)(g_Xproj + (size_t)b_g * N4H + (jg * 16 + hidB) * 4));
    }

    for (int step = 0; step < T_STEPS; ++step) {
        float accA[4] = {0.f, 0.f, 0.f, 0.f};
        float accB[4] = {0.f, 0.f, 0.f, 0.f};

        if (step > 0) {
            // ---- stage A (hi/lo): warp w stages batch rows w*2, w*2+1 ----
            const unsigned* src = g_hx + (size_t)(step - 1) * HB + (size_t)(bg * 16) * DIMH;
#pragma unroll
            for (int bb = 0; bb < 2; ++bb) {
                int brow = w * 2 + bb;
#pragma unroll
                for (int q = 0; q < 4; ++q) {
                    uint4 v = __ldcg((const uint4*)(src + (size_t)brow * DIMH + q * 128 + lane * 4));
                    uint2 hhv, llv;
                    hhv.x = (v.x & 0xffffu) | (v.y << 16);
                    hhv.y = (v.z & 0xffffu) | (v.w << 16);
                    llv.x = (v.x >> 16) | (v.y & 0xffff0000u);
                    llv.y = (v.z >> 16) | (v.w & 0xffff0000u);
                    *(uint2*)&Ah[brow * LS_W + q * 128 + lane * 4] = hhv;
                    *(uint2*)&Al[brow * LS_W + q * 128 + lane * 4] = llv;
                }
            }
            __syncthreads();

            // ---- 16 ksteps x (4 ldsm + 6 hmma), 3-pass bf16x3 ----
#pragma unroll
            for (int ks = 0; ks < 16; ++ks) {
                const uint32_t kofs = (uint32_t)(ks * 16 * 2);
                uint32_t afh[4], afl[4], bh[4], bl[4];
                ldsm_x4(afh, Ah0 + aoff + kofs);
                ldsm_x4(afl, Al0 + aoff + kofs);
                ldsm_x4(bh,  Wh0 + boff + kofs);
                ldsm_x4(bl,  Wl0 + boff + kofs);
                hmma16816(accA, afh, bh[0], bh[1]);
                hmma16816(accB, afh, bh[2], bh[3]);
                hmma16816(accA, afl, bh[0], bh[1]);
                hmma16816(accB, afl, bh[2], bh[3]);
                hmma16816(accA, afh, bl[0], bl[1]);
                hmma16816(accB, afh, bl[2], bl[3]);
            }

            // K-half 1 warps publish partials
            if (kh == 1) {
                float* rd = red + ((size_t)wn * 32 + lane) * 8;
                *(float4*)(rd)     = *(float4*)accA;
                *(float4*)(rd + 4) = *(float4*)accB;
            }
        }
        __syncthreads();

        if (w < 4) {
            if (step > 0) {
                const float* rd = red + ((size_t)wn * 32 + lane) * 8;
                float4 pA = *(const float4*)(rd);
                float4 pB = *(const float4*)(rd + 4);
                accA[0] += pA.x; accA[1] += pA.y; accA[2] += pA.z; accA[3] += pA.w;
                accB[0] += pB.x; accB[1] += pB.y; accB[2] += pB.z; accB[3] += pB.w;
            }
            // gate combine within lane pairs (xor 1)
            float eA0 = __shfl_xor_sync(0xffffffffu, accA[0], 1);
            float eA1 = __shfl_xor_sync(0xffffffffu, accA[1], 1);
            float eA2 = __shfl_xor_sync(0xffffffffu, accA[2], 1);
            float eA3 = __shfl_xor_sync(0xffffffffu, accA[3], 1);
            float eB0 = __shfl_xor_sync(0xffffffffu, accB[0], 1);
            float eB1 = __shfl_xor_sync(0xffffffffu, accB[1], 1);
            float eB2 = __shfl_xor_sync(0xffffffffu, accB[2], 1);
            float eB3 = __shfl_xor_sync(0xffffffffu, accB[3], 1);

            float zfA = (odd ? eA2 : accA[0]) + xpA.x;
            float ziA = (odd ? eA3 : accA[1]) + xpA.y;
            float zgA = (odd ? accA[2] : eA0) + xpA.z;
            float zoA = (odd ? accA[3] : eA1) + xpA.w;
            float zfB = (odd ? eB2 : accB[0]) + xpB.x;
            float ziB = (odd ? eB3 : accB[1]) + xpB.y;
            float zgB = (odd ? accB[2] : eB0) + xpB.z;
            float zoB = (odd ? accB[3] : eB1) + xpB.w;

            cstA = sigf(zfA) * cstA + sigf(ziA) * tanh_(zgA);
            cstB = sigf(zfB) * cstB + sigf(ziB) * tanh_(zgB);
            float hA = sigf(zoA) * tanh_(cstA);
            float hB = sigf(zoB) * tanh_(cstB);

            htile[b_l * 16 + hidA] = pack_hl(hA);
            htile[b_l * 16 + hidB] = pack_hl(hB);
            if (step == T_STEPS - 1) {
                ctile[b_l * 16 + hidA] = pack_hl(cstA);
                ctile[b_l * 16 + hidB] = pack_hl(cstB);
            }
            if (step + 1 < T_STEPS) {
                xpA = __ldg((const float4*)(g_Xproj
                        + ((size_t)(step + 1) * BATCH + b_g) * N4H + (jg * 16 + hidA) * 4));
                xpB = __ldg((const float4*)(g_Xproj
                        + ((size_t)(step + 1) * BATCH + b_g) * N4H + (jg * 16 + hidB) * 4));
            }
        }

        __syncthreads();
        // coalesced h' store: thread t -> (b = t>>4, hid = t&15)
        g_hx[(size_t)step * HB + (size_t)(bg * 16 + (t >> 4)) * DIMH + jg * 16 + (t & 15)]
            = htile[t];
        if (step == T_STEPS - 1)
            g_cx[(size_t)(bg * 16 + (t >> 4)) * DIMH + jg * 16 + (t & 15)] = ctile[t];

        // ---- per-domain ticket barrier (32 CTAs) ----
        __threadfence();
        __syncthreads();
        if (t == 0) {
            unsigned long long tk = atomicAdd(&g_tickd[bg * 16], 1ULL);
            unsigned long long gen = tk >> 5;
            if ((tk & 31ULL) == 31ULL) {
                __threadfence();
                g_reld[bg * 16] = gen + 1ULL;
            } else {
                while (g_reld[bg * 16] <= gen) { }
                __threadfence();
            }
        }
        __syncthreads();
    }
}

// ---------------- kernel: emit final output (unpack bf16 hi/lo -> fp32) ----------
__global__ __launch_bounds__(512) void emit_out(float* __restrict__ out, int out_size) {
    const int bx = blockIdx.x;        // 0..511: step t; 512: hx tail; 513: cx tail
    const int i4 = blockIdx.y * 512 + threadIdx.x;
    const size_t tail = (size_t)T_STEPS * HB;
    const bool write_state = (size_t)out_size >= tail + 2u * HB;

    const unsigned* src;
    float* dst;
    if (bx < T_STEPS) {
        src = g_hx + (size_t)bx * HB;
        dst = out + (size_t)bx * HB;
    } else if (bx == T_STEPS) {
        if (!write_state) return;
        src = g_hx + (size_t)(T_STEPS - 1) * HB;
        dst = out + tail;
    } else {
        if (!write_state) return;
        src = g_cx;
        dst = out + tail + HB;
    }
    uint4 v = *(const uint4*)(src + (size_t)i4 * 4);
    float4 o;
    o.x = unpack_hl(v.x);
    o.y = unpack_hl(v.y);
    o.z = unpack_hl(v.z);
    o.w = unpack_hl(v.w);
    *(float4*)(dst + (size_t)i4 * 4) = o;
}

// ---------------- launch ----------------------------------------------------------
extern "C" void kernel_launch(void* const* d_in, const int* in_sizes, int n_in,
                              void* d_out, int out_size) {
    const float* inputs = (const float*)d_in[0];
    const float* Wf = (const float*)d_in[1];
    const float* bf = (const float*)d_in[2];
    const float* Wi = (const float*)d_in[3];
    const float* bi = (const float*)d_in[4];
    const float* Wg = (const float*)d_in[5];
    const float* bg = (const float*)d_in[6];
    const float* Wo = (const float*)d_in[7];
    const float* bo = (const float*)d_in[8];

    pack_a<<<1024, 256>>>(inputs);
    pack_b<<<256, 256>>>(Wf, Wi, Wg, Wo);

    dim3 gx(N4H / XBN, MROWS / XBM);   // (16, 256)
    xproj_mma<<<gx, 256>>>(bf, bi, bg, bo);

    cudaFuncSetAttribute(lstm_mma, cudaFuncAttributeMaxDynamicSharedMemorySize, LSTM_SMEM_BYTES);
    lstm_mma<<<128, 256, LSTM_SMEM_BYTES>>>();

    emit_out<<<dim3(T_STEPS + 2, HB / 2048), 512>>>((float*)d_out, out_size);
}